// round 8
// baseline (speedup 1.0000x reference)
#include <cuda_runtime.h>
#include <cuda_fp16.h>
#include <cstdint>

// ---------------- problem constants ----------------
#define BATCH 32
#define CIN   512
#define COUT  512
#define QL    4096
#define LPAD  4098          // 1 zero row of padding at each end (conv pad=1)

// GEMM tiling: persistent, CTA tile 128(M) x 256(N), 8 warps of 64x64, 1 CTA/SM
#define TILE_M 128
#define TILE_N 256
#define TILE_K 64           // c per chunk (128B fp16 rows, swizzled)
#define CHUNKS_PER_TILE 24  // 3 taps * (512/64)
#define NSTAGE 4
#define STAGE_BYTES 49152   // A 16KB + B 32KB
#define A_OFF 0
#define B_OFF 16384
#define SMEM_DYN (NSTAGE * STAGE_BYTES)   // 192 KB

#define GRID_P 148          // persistent CTAs (1 per SM on B300; safe on 152-SM GB300)
#define NTILES ((QL / TILE_N) * (COUT / TILE_M) * BATCH)   // 16*4*32 = 2048

// ---------------- device scratch ----------------
__device__ __align__(16) __half g_qx[(size_t)BATCH * LPAD * CIN];   // [b][l+1][c] quantized x (exact ints)
__device__ __align__(16) __half g_w2[(size_t)3 * COUT * CIN];       // [k][o][c]  w'' = qw*sw*sa (fp16)

// ---------------- base-ISA helpers ----------------
__device__ __forceinline__ uint32_t smem_u32(const void* p) {
    uint32_t a;
    asm("{ .reg .u64 t; cvta.to.shared.u64 t, %1; cvt.u32.u64 %0, t; }" : "=r"(a) : "l"(p));
    return a;
}
#define SWU(u, r) (((u) ^ ((r) & 7)) << 4)   // 16B-unit swizzle within a 128B row

__device__ __forceinline__ void cp_async16(uint32_t saddr, const void* gptr) {
    asm volatile("cp.async.cg.shared.global [%0], [%1], 16;" :: "r"(saddr), "l"(gptr));
}
#define CP_COMMIT() asm volatile("cp.async.commit_group;" ::: "memory")
#define CP_WAIT(n)  asm volatile("cp.async.wait_group %0;" :: "n"(n) : "memory")

__device__ __forceinline__ void ldm_x4(uint32_t& r0, uint32_t& r1, uint32_t& r2, uint32_t& r3, uint32_t a) {
    asm volatile("ldmatrix.sync.aligned.m8n8.x4.shared.b16 {%0,%1,%2,%3}, [%4];"
                 : "=r"(r0), "=r"(r1), "=r"(r2), "=r"(r3) : "r"(a));
}
__device__ __forceinline__ void mma16816(float& c0, float& c1, float& c2, float& c3,
                                         uint32_t a0, uint32_t a1, uint32_t a2, uint32_t a3,
                                         uint32_t b0, uint32_t b1) {
    asm("mma.sync.aligned.m16n8k16.row.col.f32.f16.f16.f32 "
        "{%0,%1,%2,%3}, {%4,%5,%6,%7}, {%8,%9}, {%0,%1,%2,%3};"
        : "+f"(c0), "+f"(c1), "+f"(c2), "+f"(c3)
        : "r"(a0), "r"(a1), "r"(a2), "r"(a3), "r"(b0), "r"(b1));
}

// ---------------- kernel 1: weight prep ----------------
// w'' = clip(rint(w/sw))*sw*sa, fp16; layout [k][o][c]
__global__ void prep_w_kernel(const float* __restrict__ w,
                              const float* __restrict__ a_scale,
                              const float* __restrict__ w_scale) {
    int o = blockIdx.x, c = threadIdx.x;
    float sw = fabsf(w_scale[o]) + 1e-8f;
    float sa = fabsf(a_scale[c]) + 1e-8f;
#pragma unroll
    for (int k = 0; k < 3; k++) {
        float v = w[((size_t)o * CIN + c) * 3 + k];
        float q = fminf(fmaxf(rintf(v / sw), -128.f), 127.f);
        float wpp = (q * sw) * sa;
        g_w2[((size_t)k * COUT + o) * CIN + c] = __float2half_rn(wpp);
    }
}

// ---------------- kernel 2: zero pad rows ----------------
__global__ void pad_kernel() {
    int b = blockIdx.x, c = threadIdx.x;
    g_qx[((size_t)b * LPAD + 0) * CIN + c]          = __float2half_rn(0.f);
    g_qx[((size_t)b * LPAD + (LPAD - 1)) * CIN + c] = __float2half_rn(0.f);
}

// ---------------- kernel 3: quantize + transpose x -> g_qx[b][l+1][c] ----------------
__global__ void __launch_bounds__(256)
quant_kernel(const float* __restrict__ x, const float* __restrict__ a_scale) {
    __shared__ __half tile[128][66];          // [c_local][l_local], pad 2 halfs
    const int tid  = threadIdx.x;
    const int warp = tid >> 5;
    const int lane = tid & 31;
    const int l0 = blockIdx.x * 64;
    const int c0 = blockIdx.y * 128;
    const int b  = blockIdx.z;

#pragma unroll
    for (int j = 0; j < 16; j++) {
        int ci = j * 8 + warp;
        float s = fabsf(a_scale[c0 + ci]) + 1e-8f;
        float2 v = *reinterpret_cast<const float2*>(
            &x[((size_t)b * CIN + c0 + ci) * QL + l0 + lane * 2]);
        float q0 = fminf(fmaxf(rintf(v.x / s), -128.f), 127.f);
        float q1 = fminf(fmaxf(rintf(v.y / s), -128.f), 127.f);
        *reinterpret_cast<half2*>(&tile[ci][lane * 2]) = __floats2half2_rn(q0, q1);
    }
    __syncthreads();

#pragma unroll
    for (int it = 0; it < 8; it++) {
        int l = it * 8 + warp;
        half2 p0 = __halves2half2(tile[lane * 4 + 0][l], tile[lane * 4 + 1][l]);
        half2 p1 = __halves2half2(tile[lane * 4 + 2][l], tile[lane * 4 + 3][l]);
        uint2 w;
        w.x = *reinterpret_cast<uint32_t*>(&p0);
        w.y = *reinterpret_cast<uint32_t*>(&p1);
        *reinterpret_cast<uint2*>(
            &g_qx[((size_t)b * LPAD + l0 + l + 1) * CIN + c0 + lane * 4]) = w;
    }
}

// ---------------- kernel 4: persistent pipelined mma.sync GEMM-conv ----------------
// 148 CTAs, each walks tiles t = bid, bid+148, ...  One flat cp.async chunk
// stream spans tile boundaries; epilogue is register-only (overlaps loads).
__global__ void __launch_bounds__(256, 1)
qconv_gemm(const float* __restrict__ bias, float* __restrict__ out) {
    extern __shared__ __align__(16) char smem[];
    const uint32_t sbase = smem_u32(smem);
    const int tid  = threadIdx.x;
    const int wid  = tid >> 5;
    const int lane = tid & 31;
    const int bid  = blockIdx.x;

    // warp tile: 64(m) x 64(n); warp grid 2(m) x 4(n)
    const int wm = (wid & 1) * 64;
    const int wn = (wid >> 1) * 64;

    const uint4* gw = reinterpret_cast<const uint4*>(g_w2);
    const uint4* gx = reinterpret_cast<const uint4*>(g_qx);

    // tiles owned by this CTA
    const int ntiles = (NTILES - 1 - bid) / GRID_P + 1;   // bid < NTILES always (148 < 2048)
    const int total  = ntiles * CHUNKS_PER_TILE;

    // flat-chunk loader: j -> (tile, chunk)
    auto load_chunk_flat = [&](int j) {
        const int tl = j / CHUNKS_PER_TILE;
        const int chunk = j - tl * CHUNKS_PER_TILE;
        const int t  = bid + tl * GRID_P;
        const int b  = t >> 6;            // / (16*4)
        const int o0 = ((t >> 4) & 3) * TILE_M;
        const int L0 = (t & 15) * TILE_N;
        const int k  = chunk >> 3;        // tap 0..2
        const int cc = chunk & 7;         // c-chunk 0..7
        const uint32_t sb = sbase + (uint32_t)(j & (NSTAGE - 1)) * STAGE_BYTES;
        // A tile: 128 rows x 8 units -> 1024 units, 4 per thread
#pragma unroll
        for (int j2 = 0; j2 < 4; j2++) {
            int e = tid + j2 * 256;
            int r = e >> 3, u = e & 7;
            uint32_t so = (uint32_t)(r * 128) + SWU(u, r);
            cp_async16(sb + A_OFF + so, &gw[(size_t)(k * COUT + o0 + r) * 64 + cc * 8 + u]);
        }
        // B tile: 256 rows x 8 units -> 2048 units, 8 per thread
#pragma unroll
        for (int j2 = 0; j2 < 8; j2++) {
            int e = tid + j2 * 256;
            int r = e >> 3, u = e & 7;
            uint32_t so = (uint32_t)(r * 128) + SWU(u, r);
            cp_async16(sb + B_OFF + so, &gx[((size_t)b * LPAD + L0 + k + r) * 64 + cc * 8 + u]);
        }
    };

    float acc[4][8][4];
#pragma unroll
    for (int mi = 0; mi < 4; mi++)
#pragma unroll
        for (int nj = 0; nj < 8; nj++)
#pragma unroll
            for (int q = 0; q < 4; q++) acc[mi][nj][q] = 0.f;

    // prologue: NSTAGE-1 chunks in flight
    load_chunk_flat(0); CP_COMMIT();
    load_chunk_flat(1); CP_COMMIT();
    load_chunk_flat(2); CP_COMMIT();

    // ldmatrix lane addressing
    const int lrow = (lane & 7) + ((lane >> 3) & 1) * 8;   // row within 16-row block
    const int lcol = (lane >> 4);                          // 0/1 -> +16B (k+8)

    for (int j = 0; j < total; j++) {
        CP_WAIT(2);                 // group j complete (always-commit keeps invariant)
        __syncthreads();            // everyone's group j visible; stage j-1 free to overwrite
        if (j + NSTAGE - 1 < total) load_chunk_flat(j + NSTAGE - 1);
        CP_COMMIT();                // empty group near the tail keeps the count aligned

        const uint32_t sb = sbase + (uint32_t)(j & (NSTAGE - 1)) * STAGE_BYTES;
#pragma unroll
        for (int ks = 0; ks < 4; ks++) {
            uint32_t bf[4][4];
#pragma unroll
            for (int t = 0; t < 4; t++) {
                int r = wn + t * 16 + lrow;
                int u = ks * 2 + lcol;
                ldm_x4(bf[t][0], bf[t][1], bf[t][2], bf[t][3],
                       sb + B_OFF + r * 128 + SWU(u, r));
            }
            uint32_t af[4][4];
#pragma unroll
            for (int t = 0; t < 4; t++) {
                int r = wm + t * 16 + lrow;
                int u = ks * 2 + lcol;
                ldm_x4(af[t][0], af[t][1], af[t][2], af[t][3],
                       sb + A_OFF + r * 128 + SWU(u, r));
            }
#pragma unroll
            for (int mi = 0; mi < 4; mi++)
#pragma unroll
                for (int t = 0; t < 4; t++) {
                    mma16816(acc[mi][t*2  ][0], acc[mi][t*2  ][1], acc[mi][t*2  ][2], acc[mi][t*2  ][3],
                             af[mi][0], af[mi][1], af[mi][2], af[mi][3], bf[t][0], bf[t][2]);
                    mma16816(acc[mi][t*2+1][0], acc[mi][t*2+1][1], acc[mi][t*2+1][2], acc[mi][t*2+1][3],
                             af[mi][0], af[mi][1], af[mi][2], af[mi][3], bf[t][1], bf[t][3]);
                }
        }

        // ---- tile finished? register-only epilogue (no barrier) ----
        if ((j % CHUNKS_PER_TILE) == CHUNKS_PER_TILE - 1) {
            const int t  = bid + (j / CHUNKS_PER_TILE) * GRID_P;
            const int b  = t >> 6;
            const int o0 = ((t >> 4) & 3) * TILE_M;
            const int L0 = (t & 15) * TILE_N;
#pragma unroll
            for (int mi = 0; mi < 4; mi++) {
                int r0 = wm + mi * 16 + (lane >> 2);
                int o_a = o0 + r0, o_b = o0 + r0 + 8;
                float bv0 = bias[o_a], bv1 = bias[o_b];
                float* pa = out + ((size_t)b * COUT + o_a) * QL + L0;
                float* pb = out + ((size_t)b * COUT + o_b) * QL + L0;
#pragma unroll
                for (int nj = 0; nj < 8; nj++) {
                    int col = wn + nj * 8 + (lane & 3) * 2;
                    float2 v0 = make_float2(acc[mi][nj][0] + bv0, acc[mi][nj][1] + bv0);
                    float2 v1 = make_float2(acc[mi][nj][2] + bv1, acc[mi][nj][3] + bv1);
                    *reinterpret_cast<float2*>(pa + col) = v0;
                    *reinterpret_cast<float2*>(pb + col) = v1;
                }
            }
#pragma unroll
            for (int mi = 0; mi < 4; mi++)
#pragma unroll
                for (int nj = 0; nj < 8; nj++)
#pragma unroll
                    for (int q = 0; q < 4; q++) acc[mi][nj][q] = 0.f;
        }
    }
}

// ---------------- launch ----------------
extern "C" void kernel_launch(void* const* d_in, const int* in_sizes, int n_in,
                              void* d_out, int out_size) {
    (void)in_sizes; (void)n_in; (void)out_size;
    const float* x       = (const float*)d_in[0];
    const float* weight  = (const float*)d_in[1];
    const float* bias    = (const float*)d_in[2];
    const float* a_scale = (const float*)d_in[3];
    const float* w_scale = (const float*)d_in[4];
    float* out = (float*)d_out;

    prep_w_kernel<<<COUT, CIN>>>(weight, a_scale, w_scale);
    pad_kernel<<<BATCH, CIN>>>();
    quant_kernel<<<dim3(QL / 64, CIN / 128, BATCH), 256>>>(x, a_scale);

    cudaFuncSetAttribute(qconv_gemm, cudaFuncAttributeMaxDynamicSharedMemorySize, SMEM_DYN);
    qconv_gemm<<<GRID_P, 256, SMEM_DYN>>>(bias, out);
}

// round 9
// speedup vs baseline: 1.1282x; 1.1282x over previous
#include <cuda_runtime.h>
#include <cuda_fp16.h>
#include <cstdint>

// ---------------- problem constants ----------------
#define BATCH 32
#define CIN   512
#define COUT  512
#define QL    4096
#define LPAD  4098          // 1 zero row of padding at each end (conv pad=1)

// GEMM tiling: persistent, CTA tile 128(M) x 256(N), 16 warps of 32x64, 1 CTA/SM
#define TILE_M 128
#define TILE_N 256
#define TILE_K 64           // c per chunk (128B fp16 rows, swizzled)
#define CPT 8               // c-chunks per tile (512/64); each chunk covers ALL 3 taps
#define NSTAGE 2
// stage: A = 3 taps * 128 rows * 128B = 49152 ; B = 258 rows * 128B = 33024
#define A_TAP_BYTES 16384
#define B_OFF 49152
#define STAGE_BYTES 82176
#define SMEM_DYN (NSTAGE * STAGE_BYTES)   // 164352 B

#define GRID_P 148
#define NTILES ((QL / TILE_N) * (COUT / TILE_M) * BATCH)   // 16*4*32 = 2048

// ---------------- device scratch ----------------
__device__ __align__(16) __half g_qx[(size_t)BATCH * LPAD * CIN];   // [b][l+1][c] quantized x (exact ints)
__device__ __align__(16) __half g_w2[(size_t)3 * COUT * CIN];       // [k][o][c]  w'' = qw*sw*sa (fp16)

// ---------------- base-ISA helpers ----------------
__device__ __forceinline__ uint32_t smem_u32(const void* p) {
    uint32_t a;
    asm("{ .reg .u64 t; cvta.to.shared.u64 t, %1; cvt.u32.u64 %0, t; }" : "=r"(a) : "l"(p));
    return a;
}
#define SWU(u, r) (((u) ^ ((r) & 7)) << 4)   // 16B-unit swizzle within a 128B row

__device__ __forceinline__ void cp_async16(uint32_t saddr, const void* gptr) {
    asm volatile("cp.async.cg.shared.global [%0], [%1], 16;" :: "r"(saddr), "l"(gptr));
}
#define CP_COMMIT() asm volatile("cp.async.commit_group;" ::: "memory")
#define CP_WAIT(n)  asm volatile("cp.async.wait_group %0;" :: "n"(n) : "memory")

__device__ __forceinline__ void ldm_x4(uint32_t& r0, uint32_t& r1, uint32_t& r2, uint32_t& r3, uint32_t a) {
    asm volatile("ldmatrix.sync.aligned.m8n8.x4.shared.b16 {%0,%1,%2,%3}, [%4];"
                 : "=r"(r0), "=r"(r1), "=r"(r2), "=r"(r3) : "r"(a));
}
__device__ __forceinline__ void mma16816(float& c0, float& c1, float& c2, float& c3,
                                         uint32_t a0, uint32_t a1, uint32_t a2, uint32_t a3,
                                         uint32_t b0, uint32_t b1) {
    asm("mma.sync.aligned.m16n8k16.row.col.f32.f16.f16.f32 "
        "{%0,%1,%2,%3}, {%4,%5,%6,%7}, {%8,%9}, {%0,%1,%2,%3};"
        : "+f"(c0), "+f"(c1), "+f"(c2), "+f"(c3)
        : "r"(a0), "r"(a1), "r"(a2), "r"(a3), "r"(b0), "r"(b1));
}

// ---------------- kernel 1: weight prep ----------------
// w'' = clip(rint(w/sw))*sw*sa, fp16; layout [k][o][c]
__global__ void prep_w_kernel(const float* __restrict__ w,
                              const float* __restrict__ a_scale,
                              const float* __restrict__ w_scale) {
    int o = blockIdx.x, c = threadIdx.x;
    float sw = fabsf(w_scale[o]) + 1e-8f;
    float sa = fabsf(a_scale[c]) + 1e-8f;
#pragma unroll
    for (int k = 0; k < 3; k++) {
        float v = w[((size_t)o * CIN + c) * 3 + k];
        float q = fminf(fmaxf(rintf(v / sw), -128.f), 127.f);
        float wpp = (q * sw) * sa;
        g_w2[((size_t)k * COUT + o) * CIN + c] = __float2half_rn(wpp);
    }
}

// ---------------- kernel 2: zero pad rows ----------------
__global__ void pad_kernel() {
    int b = blockIdx.x, c = threadIdx.x;
    g_qx[((size_t)b * LPAD + 0) * CIN + c]          = __float2half_rn(0.f);
    g_qx[((size_t)b * LPAD + (LPAD - 1)) * CIN + c] = __float2half_rn(0.f);
}

// ---------------- kernel 3: quantize + transpose x -> g_qx[b][l+1][c] ----------------
__global__ void __launch_bounds__(256)
quant_kernel(const float* __restrict__ x, const float* __restrict__ a_scale) {
    __shared__ __half tile[128][66];          // [c_local][l_local], pad 2 halfs
    const int tid  = threadIdx.x;
    const int warp = tid >> 5;
    const int lane = tid & 31;
    const int l0 = blockIdx.x * 64;
    const int c0 = blockIdx.y * 128;
    const int b  = blockIdx.z;

#pragma unroll
    for (int j = 0; j < 16; j++) {
        int ci = j * 8 + warp;
        float s = fabsf(a_scale[c0 + ci]) + 1e-8f;
        float2 v = *reinterpret_cast<const float2*>(
            &x[((size_t)b * CIN + c0 + ci) * QL + l0 + lane * 2]);
        float q0 = fminf(fmaxf(rintf(v.x / s), -128.f), 127.f);
        float q1 = fminf(fmaxf(rintf(v.y / s), -128.f), 127.f);
        *reinterpret_cast<half2*>(&tile[ci][lane * 2]) = __floats2half2_rn(q0, q1);
    }
    __syncthreads();

#pragma unroll
    for (int it = 0; it < 8; it++) {
        int l = it * 8 + warp;
        half2 p0 = __halves2half2(tile[lane * 4 + 0][l], tile[lane * 4 + 1][l]);
        half2 p1 = __halves2half2(tile[lane * 4 + 2][l], tile[lane * 4 + 3][l]);
        uint2 w;
        w.x = *reinterpret_cast<uint32_t*>(&p0);
        w.y = *reinterpret_cast<uint32_t*>(&p1);
        *reinterpret_cast<uint2*>(
            &g_qx[((size_t)b * LPAD + l0 + l + 1) * CIN + c0 + lane * 4]) = w;
    }
}

// ---------------- kernel 4: persistent GEMM-conv, tap-shared B tiles ----------------
// chunk = 64 c-channels covering all 3 taps. B tile holds 258 padded rows
// (L0 .. L0+257), reused by taps via a +tap row offset in ldmatrix addressing.
__global__ void __launch_bounds__(512, 1)
qconv_gemm(const float* __restrict__ bias, float* __restrict__ out) {
    extern __shared__ __align__(16) char smem[];
    const uint32_t sbase = smem_u32(smem);
    const int tid  = threadIdx.x;
    const int wid  = tid >> 5;
    const int lane = tid & 31;
    const int bid  = blockIdx.x;

    // warp tile: 32(m) x 64(n); warp grid 4(m) x 4(n)
    const int wm = (wid & 3) * 32;
    const int wn = (wid >> 2) * 64;

    const uint4* gw = reinterpret_cast<const uint4*>(g_w2);
    const uint4* gx = reinterpret_cast<const uint4*>(g_qx);

    const int ntiles = (NTILES - 1 - bid) / GRID_P + 1;
    const int total  = ntiles * CPT;

    // flat-chunk loader: j -> (tile = j>>3, c-chunk = j&7); loads 3 A tiles + 258-row B tile
    auto load_chunk = [&](int j) {
        const int t  = bid + (j >> 3) * GRID_P;
        const int cc = j & 7;
        const int b  = t >> 6;
        const int o0 = ((t >> 4) & 3) * TILE_M;
        const int L0 = (t & 15) * TILE_N;
        const uint32_t sb = sbase + (uint32_t)(j & 1) * STAGE_BYTES;
        // A: 3 taps x 128 rows x 8 units = 3072 units, 6 per thread
#pragma unroll
        for (int k = 0; k < 3; k++)
#pragma unroll
            for (int j2 = 0; j2 < 2; j2++) {
                int e = tid + j2 * 512;
                int r = e >> 3, u = e & 7;
                cp_async16(sb + k * A_TAP_BYTES + (uint32_t)(r * 128) + SWU(u, r),
                           &gw[(size_t)(k * COUT + o0 + r) * 64 + cc * 8 + u]);
            }
        // B: 258 rows x 8 units = 2064 units (max padded row L0+257 <= 4097, in bounds)
#pragma unroll
        for (int j2 = 0; j2 < 5; j2++) {
            int e = tid + j2 * 512;
            if (e < 2064) {
                int r = e >> 3, u = e & 7;
                cp_async16(sb + B_OFF + (uint32_t)(r * 128) + SWU(u, r),
                           &gx[((size_t)b * LPAD + L0 + r) * 64 + cc * 8 + u]);
            }
        }
    };

    float acc[2][8][4];
#pragma unroll
    for (int mi = 0; mi < 2; mi++)
#pragma unroll
        for (int nj = 0; nj < 8; nj++)
#pragma unroll
            for (int q = 0; q < 4; q++) acc[mi][nj][q] = 0.f;

    // prologue
    load_chunk(0); CP_COMMIT();

    const int lrow = (lane & 7) + ((lane >> 3) & 1) * 8;
    const int lcol = (lane >> 4);

    for (int j = 0; j < total; j++) {
        // load j+1 into the stage consumed at iter j-1 (trailing sync of j-1 protects it)
        if (j + 1 < total) load_chunk(j + 1);
        CP_COMMIT();
        CP_WAIT(1);                // group j complete
        __syncthreads();           // group j visible CTA-wide

        const uint32_t sb = sbase + (uint32_t)(j & 1) * STAGE_BYTES;
#pragma unroll
        for (int tap = 0; tap < 3; tap++) {
#pragma unroll
            for (int ks = 0; ks < 4; ks++) {
                const int u = ks * 2 + lcol;
                uint32_t bf[4][4];
#pragma unroll
                for (int t = 0; t < 4; t++) {
                    int r = wn + t * 16 + lrow + tap;
                    ldm_x4(bf[t][0], bf[t][1], bf[t][2], bf[t][3],
                           sb + B_OFF + r * 128 + SWU(u, r));
                }
                uint32_t af[2][4];
#pragma unroll
                for (int t = 0; t < 2; t++) {
                    int r = wm + t * 16 + lrow;
                    ldm_x4(af[t][0], af[t][1], af[t][2], af[t][3],
                           sb + tap * A_TAP_BYTES + r * 128 + SWU(u, r));
                }
#pragma unroll
                for (int mi = 0; mi < 2; mi++)
#pragma unroll
                    for (int t = 0; t < 4; t++) {
                        mma16816(acc[mi][t*2  ][0], acc[mi][t*2  ][1], acc[mi][t*2  ][2], acc[mi][t*2  ][3],
                                 af[mi][0], af[mi][1], af[mi][2], af[mi][3], bf[t][0], bf[t][2]);
                        mma16816(acc[mi][t*2+1][0], acc[mi][t*2+1][1], acc[mi][t*2+1][2], acc[mi][t*2+1][3],
                                 af[mi][0], af[mi][1], af[mi][2], af[mi][3], bf[t][1], bf[t][3]);
                    }
            }
        }

        // ---- tile finished? register-only epilogue ----
        if ((j & 7) == 7) {
            const int t  = bid + (j >> 3) * GRID_P;
            const int b  = t >> 6;
            const int o0 = ((t >> 4) & 3) * TILE_M;
            const int L0 = (t & 15) * TILE_N;
#pragma unroll
            for (int mi = 0; mi < 2; mi++) {
                int r0 = wm + mi * 16 + (lane >> 2);
                int o_a = o0 + r0, o_b = o0 + r0 + 8;
                float bv0 = bias[o_a], bv1 = bias[o_b];
                float* pa = out + ((size_t)b * COUT + o_a) * QL + L0;
                float* pb = out + ((size_t)b * COUT + o_b) * QL + L0;
#pragma unroll
                for (int nj = 0; nj < 8; nj++) {
                    int col = wn + nj * 8 + (lane & 3) * 2;
                    float2 v0 = make_float2(acc[mi][nj][0] + bv0, acc[mi][nj][1] + bv0);
                    float2 v1 = make_float2(acc[mi][nj][2] + bv1, acc[mi][nj][3] + bv1);
                    *reinterpret_cast<float2*>(pa + col) = v0;
                    *reinterpret_cast<float2*>(pb + col) = v1;
                }
            }
#pragma unroll
            for (int mi = 0; mi < 2; mi++)
#pragma unroll
                for (int nj = 0; nj < 8; nj++)
#pragma unroll
                    for (int q = 0; q < 4; q++) acc[mi][nj][q] = 0.f;
        }
        __syncthreads();           // all warps done with stage j before it is reloaded
    }
}

// ---------------- launch ----------------
extern "C" void kernel_launch(void* const* d_in, const int* in_sizes, int n_in,
                              void* d_out, int out_size) {
    (void)in_sizes; (void)n_in; (void)out_size;
    const float* x       = (const float*)d_in[0];
    const float* weight  = (const float*)d_in[1];
    const float* bias    = (const float*)d_in[2];
    const float* a_scale = (const float*)d_in[3];
    const float* w_scale = (const float*)d_in[4];
    float* out = (float*)d_out;

    prep_w_kernel<<<COUT, CIN>>>(weight, a_scale, w_scale);
    pad_kernel<<<BATCH, CIN>>>();
    quant_kernel<<<dim3(QL / 64, CIN / 128, BATCH), 256>>>(x, a_scale);

    cudaFuncSetAttribute(qconv_gemm, cudaFuncAttributeMaxDynamicSharedMemorySize, SMEM_DYN);
    qconv_gemm<<<GRID_P, 512, SMEM_DYN>>>(bias, out);
}

// round 11
// speedup vs baseline: 1.1814x; 1.0472x over previous
#include <cuda_runtime.h>
#include <cuda_fp16.h>
#include <cstdint>

// ---------------- problem constants ----------------
#define BATCH 32
#define CIN   512
#define COUT  512
#define QL    4096
#define LPAD  4098          // 1 zero row of padding at each end (conv pad=1)

// GEMM tiling: persistent, CTA tile 128(M) x 256(N), 16 warps of 32x64, 1 CTA/SM
#define TILE_M 128
#define TILE_N 256
#define TILE_K 64           // c per chunk (128B fp16 rows, swizzled)
#define CPT 8               // c-chunks per tile (512/64); each chunk covers ALL 3 taps
#define NSTAGE 2
// stage: A = 3 taps * 128 rows * 128B = 49152 ; B = 258 rows * 128B = 33024
#define A_TAP_BYTES 16384
#define B_OFF 49152
#define STAGE_BYTES 82176
#define SMEM_DYN (NSTAGE * STAGE_BYTES)   // 164352 B

#define GRID_P 148
#define NTILES ((QL / TILE_N) * (COUT / TILE_M) * BATCH)   // 16*4*32 = 2048

// ---------------- device scratch ----------------
__device__ __align__(16) __half g_qx[(size_t)BATCH * LPAD * CIN];   // [b][l+1][c] quantized x (exact ints)
__device__ __align__(16) __half g_w2[(size_t)3 * COUT * CIN];       // [k][o][c]  w'' = qw*sw*sa (fp16)

// ---------------- base-ISA helpers ----------------
__device__ __forceinline__ uint32_t smem_u32(const void* p) {
    uint32_t a;
    asm("{ .reg .u64 t; cvta.to.shared.u64 t, %1; cvt.u32.u64 %0, t; }" : "=r"(a) : "l"(p));
    return a;
}
#define SWU(u, r) (((u) ^ ((r) & 7)) << 4)   // 16B-unit swizzle within a 128B row

__device__ __forceinline__ void cp_async16(uint32_t saddr, const void* gptr) {
    asm volatile("cp.async.cg.shared.global [%0], [%1], 16;" :: "r"(saddr), "l"(gptr));
}
#define CP_COMMIT() asm volatile("cp.async.commit_group;" ::: "memory")
#define CP_WAIT(n)  asm volatile("cp.async.wait_group %0;" :: "n"(n) : "memory")

__device__ __forceinline__ void ldm_x4(uint32_t& r0, uint32_t& r1, uint32_t& r2, uint32_t& r3, uint32_t a) {
    asm volatile("ldmatrix.sync.aligned.m8n8.x4.shared.b16 {%0,%1,%2,%3}, [%4];"
                 : "=r"(r0), "=r"(r1), "=r"(r2), "=r"(r3) : "r"(a));
}
__device__ __forceinline__ void mma16816(float& c0, float& c1, float& c2, float& c3,
                                         uint32_t a0, uint32_t a1, uint32_t a2, uint32_t a3,
                                         uint32_t b0, uint32_t b1) {
    asm("mma.sync.aligned.m16n8k16.row.col.f32.f16.f16.f32 "
        "{%0,%1,%2,%3}, {%4,%5,%6,%7}, {%8,%9}, {%0,%1,%2,%3};"
        : "+f"(c0), "+f"(c1), "+f"(c2), "+f"(c3)
        : "r"(a0), "r"(a1), "r"(a2), "r"(a3), "r"(b0), "r"(b1));
}

// ---------------- kernel 1: weight prep ----------------
// w'' = clip(rint(w/sw))*sw*sa, fp16; layout [k][o][c]
__global__ void prep_w_kernel(const float* __restrict__ w,
                              const float* __restrict__ a_scale,
                              const float* __restrict__ w_scale) {
    int o = blockIdx.x, c = threadIdx.x;
    float sw = fabsf(w_scale[o]) + 1e-8f;
    float sa = fabsf(a_scale[c]) + 1e-8f;
#pragma unroll
    for (int k = 0; k < 3; k++) {
        float v = w[((size_t)o * CIN + c) * 3 + k];
        float q = fminf(fmaxf(rintf(v / sw), -128.f), 127.f);
        float wpp = (q * sw) * sa;
        g_w2[((size_t)k * COUT + o) * CIN + c] = __float2half_rn(wpp);
    }
}

// ---------------- kernel 2: zero pad rows ----------------
__global__ void pad_kernel() {
    int b = blockIdx.x, c = threadIdx.x;
    g_qx[((size_t)b * LPAD + 0) * CIN + c]          = __float2half_rn(0.f);
    g_qx[((size_t)b * LPAD + (LPAD - 1)) * CIN + c] = __float2half_rn(0.f);
}

// ---------------- kernel 3: quantize + transpose x -> g_qx[b][l+1][c] ----------------
__global__ void __launch_bounds__(256)
quant_kernel(const float* __restrict__ x, const float* __restrict__ a_scale) {
    __shared__ __half tile[128][66];          // [c_local][l_local], pad 2 halfs
    const int tid  = threadIdx.x;
    const int warp = tid >> 5;
    const int lane = tid & 31;
    const int l0 = blockIdx.x * 64;
    const int c0 = blockIdx.y * 128;
    const int b  = blockIdx.z;

#pragma unroll
    for (int j = 0; j < 16; j++) {
        int ci = j * 8 + warp;
        float s = fabsf(a_scale[c0 + ci]) + 1e-8f;
        float2 v = *reinterpret_cast<const float2*>(
            &x[((size_t)b * CIN + c0 + ci) * QL + l0 + lane * 2]);
        float q0 = fminf(fmaxf(rintf(v.x / s), -128.f), 127.f);
        float q1 = fminf(fmaxf(rintf(v.y / s), -128.f), 127.f);
        *reinterpret_cast<half2*>(&tile[ci][lane * 2]) = __floats2half2_rn(q0, q1);
    }
    __syncthreads();

#pragma unroll
    for (int it = 0; it < 8; it++) {
        int l = it * 8 + warp;
        half2 p0 = __halves2half2(tile[lane * 4 + 0][l], tile[lane * 4 + 1][l]);
        half2 p1 = __halves2half2(tile[lane * 4 + 2][l], tile[lane * 4 + 3][l]);
        uint2 w;
        w.x = *reinterpret_cast<uint32_t*>(&p0);
        w.y = *reinterpret_cast<uint32_t*>(&p1);
        *reinterpret_cast<uint2*>(
            &g_qx[((size_t)b * LPAD + l0 + l + 1) * CIN + c0 + lane * 4]) = w;
    }
}

// ---------------- kernel 4: persistent GEMM-conv, tap-shared B, single barrier ----------------
// mainloop ordering per chunk j:  wait(0) -> __syncthreads -> [tap0 | issue loads j+1 | tap1 tap2]
// Safety: top barrier proves (a) all group-j copies drained+visible, (b) all warps
// finished compute(j-1), so overwriting stage (j-1)&1 mid-chunk is race-free.
__global__ void __launch_bounds__(512, 1)
qconv_gemm(const float* __restrict__ bias, float* __restrict__ out) {
    extern __shared__ __align__(16) char smem[];
    const uint32_t sbase = smem_u32(smem);
    const int tid  = threadIdx.x;
    const int wid  = tid >> 5;
    const int lane = tid & 31;
    const int bid  = blockIdx.x;

    // warp tile: 32(m) x 64(n); warp grid 4(m) x 4(n)
    const int wm = (wid & 3) * 32;
    const int wn = (wid >> 2) * 64;

    const uint4* gw = reinterpret_cast<const uint4*>(g_w2);
    const uint4* gx = reinterpret_cast<const uint4*>(g_qx);

    const int ntiles = (NTILES - 1 - bid) / GRID_P + 1;
    const int total  = ntiles * CPT;

    // flat-chunk loader: j -> (tile = j>>3, c-chunk = j&7); loads 3 A tiles + 258-row B tile
    auto load_chunk = [&](int j) {
        const int t  = bid + (j >> 3) * GRID_P;
        const int cc = j & 7;
        const int b  = t >> 6;
        const int o0 = ((t >> 4) & 3) * TILE_M;
        const int L0 = (t & 15) * TILE_N;
        const uint32_t sb = sbase + (uint32_t)(j & 1) * STAGE_BYTES;
        // A: 3 taps x 128 rows x 8 units = 3072 units, 6 per thread
#pragma unroll
        for (int k = 0; k < 3; k++)
#pragma unroll
            for (int j2 = 0; j2 < 2; j2++) {
                int e = tid + j2 * 512;
                int r = e >> 3, u = e & 7;
                cp_async16(sb + k * A_TAP_BYTES + (uint32_t)(r * 128) + SWU(u, r),
                           &gw[(size_t)(k * COUT + o0 + r) * 64 + cc * 8 + u]);
            }
        // B: 258 rows x 8 units = 2064 units (max padded row L0+257 <= 4097, in bounds)
#pragma unroll
        for (int j2 = 0; j2 < 5; j2++) {
            int e = tid + j2 * 512;
            if (e < 2064) {
                int r = e >> 3, u = e & 7;
                cp_async16(sb + B_OFF + (uint32_t)(r * 128) + SWU(u, r),
                           &gx[((size_t)b * LPAD + L0 + r) * 64 + cc * 8 + u]);
            }
        }
    };

    float acc[2][8][4];
#pragma unroll
    for (int mi = 0; mi < 2; mi++)
#pragma unroll
        for (int nj = 0; nj < 8; nj++)
#pragma unroll
            for (int q = 0; q < 4; q++) acc[mi][nj][q] = 0.f;

    const int lrow = (lane & 7) + ((lane >> 3) & 1) * 8;
    const int lcol = (lane >> 4);

    // one tap of compute against stage sb
    auto compute_tap = [&](uint32_t sb, int tap) {
#pragma unroll
        for (int ks = 0; ks < 4; ks++) {
            const int u = ks * 2 + lcol;
            uint32_t bf[4][4];
#pragma unroll
            for (int t = 0; t < 4; t++) {
                int r = wn + t * 16 + lrow + tap;
                ldm_x4(bf[t][0], bf[t][1], bf[t][2], bf[t][3],
                       sb + B_OFF + r * 128 + SWU(u, r));
            }
            uint32_t af[2][4];
#pragma unroll
            for (int t = 0; t < 2; t++) {
                int r = wm + t * 16 + lrow;
                ldm_x4(af[t][0], af[t][1], af[t][2], af[t][3],
                       sb + tap * A_TAP_BYTES + r * 128 + SWU(u, r));
            }
#pragma unroll
            for (int mi = 0; mi < 2; mi++)
#pragma unroll
                for (int t = 0; t < 4; t++) {
                    mma16816(acc[mi][t*2  ][0], acc[mi][t*2  ][1], acc[mi][t*2  ][2], acc[mi][t*2  ][3],
                             af[mi][0], af[mi][1], af[mi][2], af[mi][3], bf[t][0], bf[t][2]);
                    mma16816(acc[mi][t*2+1][0], acc[mi][t*2+1][1], acc[mi][t*2+1][2], acc[mi][t*2+1][3],
                             af[mi][0], af[mi][1], af[mi][2], af[mi][3], bf[t][1], bf[t][3]);
                }
        }
    };

    // prologue
    load_chunk(0); CP_COMMIT();

    for (int j = 0; j < total; j++) {
        CP_WAIT(0);                // this thread's copies (group j) complete
        __syncthreads();           // all threads waited -> stage j&1 visible; compute(j-1) done CTA-wide

        const uint32_t sb = sbase + (uint32_t)(j & 1) * STAGE_BYTES;
        compute_tap(sb, 0);
        if (j + 1 < total) { load_chunk(j + 1); CP_COMMIT(); }   // issued under tap1/2 HMMA shadow
        compute_tap(sb, 1);
        compute_tap(sb, 2);

        // ---- tile finished? register-only epilogue (overlaps in-flight loads) ----
        if ((j & 7) == 7) {
            const int t  = bid + (j >> 3) * GRID_P;
            const int b  = t >> 6;
            const int o0 = ((t >> 4) & 3) * TILE_M;
            const int L0 = (t & 15) * TILE_N;
#pragma unroll
            for (int mi = 0; mi < 2; mi++) {
                int r0 = wm + mi * 16 + (lane >> 2);
                int o_a = o0 + r0, o_b = o0 + r0 + 8;
                float bv0 = bias[o_a], bv1 = bias[o_b];
                float* pa = out + ((size_t)b * COUT + o_a) * QL + L0;
                float* pb = out + ((size_t)b * COUT + o_b) * QL + L0;
#pragma unroll
                for (int nj = 0; nj < 8; nj++) {
                    int col = wn + nj * 8 + (lane & 3) * 2;
                    float2 v0 = make_float2(acc[mi][nj][0] + bv0, acc[mi][nj][1] + bv0);
                    float2 v1 = make_float2(acc[mi][nj][2] + bv1, acc[mi][nj][3] + bv1);
                    *reinterpret_cast<float2*>(pa + col) = v0;
                    *reinterpret_cast<float2*>(pb + col) = v1;
                }
            }
#pragma unroll
            for (int mi = 0; mi < 2; mi++)
#pragma unroll
                for (int nj = 0; nj < 8; nj++)
#pragma unroll
                    for (int q = 0; q < 4; q++) acc[mi][nj][q] = 0.f;
        }
    }
}

// ---------------- launch ----------------
extern "C" void kernel_launch(void* const* d_in, const int* in_sizes, int n_in,
                              void* d_out, int out_size) {
    (void)in_sizes; (void)n_in; (void)out_size;
    const float* x       = (const float*)d_in[0];
    const float* weight  = (const float*)d_in[1];
    const float* bias    = (const float*)d_in[2];
    const float* a_scale = (const float*)d_in[3];
    const float* w_scale = (const float*)d_in[4];
    float* out = (float*)d_out;

    prep_w_kernel<<<COUT, CIN>>>(weight, a_scale, w_scale);
    pad_kernel<<<BATCH, CIN>>>();
    quant_kernel<<<dim3(QL / 64, CIN / 128, BATCH), 256>>>(x, a_scale);

    cudaFuncSetAttribute(qconv_gemm, cudaFuncAttributeMaxDynamicSharedMemorySize, SMEM_DYN);
    qconv_gemm<<<GRID_P, 512, SMEM_DYN>>>(bias, out);
}

// round 12
// speedup vs baseline: 1.2135x; 1.0272x over previous
#include <cuda_runtime.h>
#include <cuda_fp16.h>
#include <cstdint>

// ---------------- problem constants ----------------
#define BATCH 32
#define CIN   512
#define COUT  512
#define QL    4096
#define LPAD  4098          // 1 zero row of padding at each end (conv pad=1)

// GEMM tiling: persistent, CTA tile 128(M) x 256(N), 16 warps of 32x64, 1 CTA/SM
#define TILE_M 128
#define TILE_N 256
#define TILE_K 64           // c per chunk (128B fp16 rows, swizzled)
#define CPT 8               // c-chunks per tile (512/64); each chunk covers ALL 3 taps
#define NSTAGE 2
// stage: A = 3 taps * 128 rows * 128B = 49152 ; B = 258 rows * 128B = 33024
#define A_TAP_BYTES 16384
#define B_OFF 49152
#define STAGE_BYTES 82176
#define SMEM_DYN (NSTAGE * STAGE_BYTES)   // 164352 B

#define GRID_P 148
#define NTILES ((QL / TILE_N) * (COUT / TILE_M) * BATCH)   // 16*4*32 = 2048

// ---------------- device scratch ----------------
__device__ __align__(16) __half g_qx[(size_t)BATCH * LPAD * CIN];   // [b][l+1][c] quantized x (exact ints)
__device__ __align__(16) __half g_w2[(size_t)3 * COUT * CIN];       // [k][o][c]  w'' = qw*sw*sa (fp16)

// ---------------- base-ISA helpers ----------------
__device__ __forceinline__ uint32_t smem_u32(const void* p) {
    uint32_t a;
    asm("{ .reg .u64 t; cvta.to.shared.u64 t, %1; cvt.u32.u64 %0, t; }" : "=r"(a) : "l"(p));
    return a;
}
#define SWU(u, r) (((u) ^ ((r) & 7)) << 4)   // 16B-unit swizzle within a 128B row

__device__ __forceinline__ void cp_async16(uint32_t saddr, const void* gptr) {
    asm volatile("cp.async.cg.shared.global [%0], [%1], 16;" :: "r"(saddr), "l"(gptr));
}
#define CP_COMMIT() asm volatile("cp.async.commit_group;" ::: "memory")
#define CP_WAIT(n)  asm volatile("cp.async.wait_group %0;" :: "n"(n) : "memory")

__device__ __forceinline__ void ldm_x4(uint32_t& r0, uint32_t& r1, uint32_t& r2, uint32_t& r3, uint32_t a) {
    asm volatile("ldmatrix.sync.aligned.m8n8.x4.shared.b16 {%0,%1,%2,%3}, [%4];"
                 : "=r"(r0), "=r"(r1), "=r"(r2), "=r"(r3) : "r"(a));
}
__device__ __forceinline__ void mma16816(float& c0, float& c1, float& c2, float& c3,
                                         uint32_t a0, uint32_t a1, uint32_t a2, uint32_t a3,
                                         uint32_t b0, uint32_t b1) {
    asm("mma.sync.aligned.m16n8k16.row.col.f32.f16.f16.f32 "
        "{%0,%1,%2,%3}, {%4,%5,%6,%7}, {%8,%9}, {%0,%1,%2,%3};"
        : "+f"(c0), "+f"(c1), "+f"(c2), "+f"(c3)
        : "r"(a0), "r"(a1), "r"(a2), "r"(a3), "r"(b0), "r"(b1));
}

// ---------------- kernel 1: weight prep ----------------
// w'' = clip(rint(w/sw))*sw*sa, fp16; layout [k][o][c]
__global__ void prep_w_kernel(const float* __restrict__ w,
                              const float* __restrict__ a_scale,
                              const float* __restrict__ w_scale) {
    int o = blockIdx.x, c = threadIdx.x;
    float sw = fabsf(w_scale[o]) + 1e-8f;
    float sa = fabsf(a_scale[c]) + 1e-8f;
#pragma unroll
    for (int k = 0; k < 3; k++) {
        float v = w[((size_t)o * CIN + c) * 3 + k];
        float q = fminf(fmaxf(rintf(v / sw), -128.f), 127.f);
        float wpp = (q * sw) * sa;
        g_w2[((size_t)k * COUT + o) * CIN + c] = __float2half_rn(wpp);
    }
}

// ---------------- kernel 2: quantize + transpose x -> g_qx[b][l+1][c] ----------------
// Conflict-free both phases via permuted smem rows: store channel ci at row
// sigma(ci) = (ci&3)*32 + (ci>>2); write phase reads rows lane+32k (stride 33
// halfs between lanes -> odd -> no bank conflicts) and gets 4 contiguous
// channels 4*lane+k for a uint2 store. Pad rows fused in (l-block 0 / last).
__global__ void __launch_bounds__(256)
quant_kernel(const float* __restrict__ x, const float* __restrict__ a_scale) {
    __shared__ __half tile[128][66];
    const int tid  = threadIdx.x;
    const int warp = tid >> 5;
    const int lane = tid & 31;
    const int l0 = blockIdx.x * 64;
    const int c0 = blockIdx.y * 128;
    const int b  = blockIdx.z;

    // fused zero-padding of rows l=-1 and l=QL (each block covers its c-slice)
    if (blockIdx.x == 0 && tid < 32) {
        *reinterpret_cast<uint2*>(&g_qx[((size_t)b * LPAD + 0) * CIN + c0 + tid * 4]) =
            make_uint2(0u, 0u);
    }
    if (blockIdx.x == gridDim.x - 1 && tid < 32) {
        *reinterpret_cast<uint2*>(&g_qx[((size_t)b * LPAD + (LPAD - 1)) * CIN + c0 + tid * 4]) =
            make_uint2(0u, 0u);
    }

    // read phase: each warp reads one c-row of 64 l (256B) per j; permuted row store
#pragma unroll
    for (int j = 0; j < 16; j++) {
        int ci = j * 8 + warp;
        int row = (ci & 3) * 32 + (ci >> 2);
        float s = fabsf(a_scale[c0 + ci]) + 1e-8f;
        float2 v = *reinterpret_cast<const float2*>(
            &x[((size_t)b * CIN + c0 + ci) * QL + l0 + lane * 2]);
        float q0 = fminf(fmaxf(rintf(v.x / s), -128.f), 127.f);
        float q1 = fminf(fmaxf(rintf(v.y / s), -128.f), 127.f);
        *reinterpret_cast<half2*>(&tile[row][lane * 2]) = __floats2half2_rn(q0, q1);
    }
    __syncthreads();

    // write phase: rows lane+32k hold channels 4*lane+k; conflict-free column reads
#pragma unroll
    for (int it = 0; it < 8; it++) {
        int l = it * 8 + warp;
        half2 p0 = __halves2half2(tile[lane +  0][l], tile[lane + 32][l]);
        half2 p1 = __halves2half2(tile[lane + 64][l], tile[lane + 96][l]);
        uint2 w;
        w.x = *reinterpret_cast<uint32_t*>(&p0);
        w.y = *reinterpret_cast<uint32_t*>(&p1);
        *reinterpret_cast<uint2*>(
            &g_qx[((size_t)b * LPAD + l0 + l + 1) * CIN + c0 + lane * 4]) = w;
    }
}

// ---------------- kernel 3: persistent GEMM-conv (unchanged from R11 winner) ----------------
__global__ void __launch_bounds__(512, 1)
qconv_gemm(const float* __restrict__ bias, float* __restrict__ out) {
    extern __shared__ __align__(16) char smem[];
    const uint32_t sbase = smem_u32(smem);
    const int tid  = threadIdx.x;
    const int wid  = tid >> 5;
    const int lane = tid & 31;
    const int bid  = blockIdx.x;

    const int wm = (wid & 3) * 32;
    const int wn = (wid >> 2) * 64;

    const uint4* gw = reinterpret_cast<const uint4*>(g_w2);
    const uint4* gx = reinterpret_cast<const uint4*>(g_qx);

    const int ntiles = (NTILES - 1 - bid) / GRID_P + 1;
    const int total  = ntiles * CPT;

    auto load_chunk = [&](int j) {
        const int t  = bid + (j >> 3) * GRID_P;
        const int cc = j & 7;
        const int b  = t >> 6;
        const int o0 = ((t >> 4) & 3) * TILE_M;
        const int L0 = (t & 15) * TILE_N;
        const uint32_t sb = sbase + (uint32_t)(j & 1) * STAGE_BYTES;
#pragma unroll
        for (int k = 0; k < 3; k++)
#pragma unroll
            for (int j2 = 0; j2 < 2; j2++) {
                int e = tid + j2 * 512;
                int r = e >> 3, u = e & 7;
                cp_async16(sb + k * A_TAP_BYTES + (uint32_t)(r * 128) + SWU(u, r),
                           &gw[(size_t)(k * COUT + o0 + r) * 64 + cc * 8 + u]);
            }
#pragma unroll
        for (int j2 = 0; j2 < 5; j2++) {
            int e = tid + j2 * 512;
            if (e < 2064) {
                int r = e >> 3, u = e & 7;
                cp_async16(sb + B_OFF + (uint32_t)(r * 128) + SWU(u, r),
                           &gx[((size_t)b * LPAD + L0 + r) * 64 + cc * 8 + u]);
            }
        }
    };

    float acc[2][8][4];
#pragma unroll
    for (int mi = 0; mi < 2; mi++)
#pragma unroll
        for (int nj = 0; nj < 8; nj++)
#pragma unroll
            for (int q = 0; q < 4; q++) acc[mi][nj][q] = 0.f;

    const int lrow = (lane & 7) + ((lane >> 3) & 1) * 8;
    const int lcol = (lane >> 4);

    auto compute_tap = [&](uint32_t sb, int tap) {
#pragma unroll
        for (int ks = 0; ks < 4; ks++) {
            const int u = ks * 2 + lcol;
            uint32_t bf[4][4];
#pragma unroll
            for (int t = 0; t < 4; t++) {
                int r = wn + t * 16 + lrow + tap;
                ldm_x4(bf[t][0], bf[t][1], bf[t][2], bf[t][3],
                       sb + B_OFF + r * 128 + SWU(u, r));
            }
            uint32_t af[2][4];
#pragma unroll
            for (int t = 0; t < 2; t++) {
                int r = wm + t * 16 + lrow;
                ldm_x4(af[t][0], af[t][1], af[t][2], af[t][3],
                       sb + tap * A_TAP_BYTES + r * 128 + SWU(u, r));
            }
#pragma unroll
            for (int mi = 0; mi < 2; mi++)
#pragma unroll
                for (int t = 0; t < 4; t++) {
                    mma16816(acc[mi][t*2  ][0], acc[mi][t*2  ][1], acc[mi][t*2  ][2], acc[mi][t*2  ][3],
                             af[mi][0], af[mi][1], af[mi][2], af[mi][3], bf[t][0], bf[t][2]);
                    mma16816(acc[mi][t*2+1][0], acc[mi][t*2+1][1], acc[mi][t*2+1][2], acc[mi][t*2+1][3],
                             af[mi][0], af[mi][1], af[mi][2], af[mi][3], bf[t][1], bf[t][3]);
                }
        }
    };

    load_chunk(0); CP_COMMIT();

    for (int j = 0; j < total; j++) {
        CP_WAIT(0);
        __syncthreads();

        const uint32_t sb = sbase + (uint32_t)(j & 1) * STAGE_BYTES;
        compute_tap(sb, 0);
        if (j + 1 < total) { load_chunk(j + 1); CP_COMMIT(); }
        compute_tap(sb, 1);
        compute_tap(sb, 2);

        if ((j & 7) == 7) {
            const int t  = bid + (j >> 3) * GRID_P;
            const int b  = t >> 6;
            const int o0 = ((t >> 4) & 3) * TILE_M;
            const int L0 = (t & 15) * TILE_N;
#pragma unroll
            for (int mi = 0; mi < 2; mi++) {
                int r0 = wm + mi * 16 + (lane >> 2);
                int o_a = o0 + r0, o_b = o0 + r0 + 8;
                float bv0 = bias[o_a], bv1 = bias[o_b];
                float* pa = out + ((size_t)b * COUT + o_a) * QL + L0;
                float* pb = out + ((size_t)b * COUT + o_b) * QL + L0;
#pragma unroll
                for (int nj = 0; nj < 8; nj++) {
                    int col = wn + nj * 8 + (lane & 3) * 2;
                    float2 v0 = make_float2(acc[mi][nj][0] + bv0, acc[mi][nj][1] + bv0);
                    float2 v1 = make_float2(acc[mi][nj][2] + bv1, acc[mi][nj][3] + bv1);
                    *reinterpret_cast<float2*>(pa + col) = v0;
                    *reinterpret_cast<float2*>(pb + col) = v1;
                }
            }
#pragma unroll
            for (int mi = 0; mi < 2; mi++)
#pragma unroll
                for (int nj = 0; nj < 8; nj++)
#pragma unroll
                    for (int q = 0; q < 4; q++) acc[mi][nj][q] = 0.f;
        }
    }
}

// ---------------- launch ----------------
extern "C" void kernel_launch(void* const* d_in, const int* in_sizes, int n_in,
                              void* d_out, int out_size) {
    (void)in_sizes; (void)n_in; (void)out_size;
    const float* x       = (const float*)d_in[0];
    const float* weight  = (const float*)d_in[1];
    const float* bias    = (const float*)d_in[2];
    const float* a_scale = (const float*)d_in[3];
    const float* w_scale = (const float*)d_in[4];
    float* out = (float*)d_out;

    prep_w_kernel<<<COUT, CIN>>>(weight, a_scale, w_scale);
    quant_kernel<<<dim3(QL / 64, CIN / 128, BATCH), 256>>>(x, a_scale);

    cudaFuncSetAttribute(qconv_gemm, cudaFuncAttributeMaxDynamicSharedMemorySize, SMEM_DYN);
    qconv_gemm<<<GRID_P, 512, SMEM_DYN>>>(bias, out);
}